// round 12
// baseline (speedup 1.0000x reference)
#include <cuda_runtime.h>
#include <cuda_bf16.h>

// LSTM: B=32768, T=28, IN=28, H=8, NC=10. Gate order i,j,f,o. Forget bias 1.0.
// R12: WEIGHTS IN REGISTERS. R11 proved the smem crossbar is the wall (L1
// 71.3%): every warp re-read the full weight set per step. Now 8 lanes per
// sample; lane m owns hidden unit m = gate columns {m, 8+m, 16+m, 24+m},
// i.e. 36 rows x 2 f32x2 weight pairs = 144 regs gathered ONCE from smem.
// Hot loop: 72 FFMA2 on 2 accumulators (A/B alternation covers FFMA lat 4),
// 5 exact activations per lane (no redundancy), 7-shfl butterfly to
// all-gather h. Butterfly order (pos p = lane m^p) is baked into the h-row
// weight gather at init. Forget bias folded into the f bias. Zero LDS in the
// hot loop. 262144 threads = 8192 warps.

#define BTOT 32768
#define TSTEPS 28
#define INDIM 28
#define HID 8
#define NCLS 10
#define BLK 128

typedef unsigned long long u64;

__device__ __forceinline__ u64 pack2(float x) {
    u64 r; unsigned xi = __float_as_uint(x);
    asm("mov.b64 %0, {%1, %1};" : "=l"(r) : "r"(xi));
    return r;
}

__device__ __forceinline__ u64 packab(float a, float b) {
    u64 r; unsigned ai = __float_as_uint(a), bi = __float_as_uint(b);
    asm("mov.b64 %0, {%1, %2};" : "=l"(r) : "r"(ai), "r"(bi));
    return r;
}

__device__ __forceinline__ u64 fma2(u64 a, u64 b, u64 c) {
    u64 d;
    asm("fma.rn.f32x2 %0, %1, %2, %3;" : "=l"(d) : "l"(a), "l"(b), "l"(c));
    return d;
}

__device__ __forceinline__ void unpack2(u64 v, float& lo, float& hi) {
    unsigned a, b;
    asm("mov.b64 {%0, %1}, %2;" : "=r"(a), "=r"(b) : "l"(v));
    lo = __uint_as_float(a);
    hi = __uint_as_float(b);
}

__device__ __forceinline__ float sigf(float x) {
    float e = __expf(-x);
    return __fdividef(1.0f, 1.0f + e);
}

__device__ __forceinline__ float tanh_exact(float x) {
    // tanh(x) = 1 - 2/(e^{2x}+1). Overflow of e -> +1; underflow -> -1.
    float e = __expf(2.0f * x);
    return 1.0f - __fdividef(2.0f, e + 1.0f);
}

__global__ __launch_bounds__(BLK)
void lstm_kernel(const float* __restrict__ x,
                 const float* __restrict__ W,      // [36, 32] row-major
                 const float* __restrict__ bias,   // [32]
                 const float* __restrict__ ow,     // [8, 10]
                 const float* __restrict__ ob,     // [10]
                 float* __restrict__ out)          // [B, 10]
{
    __shared__ float sWraw[(INDIM + HID) * 32];   // 36 x 32, row-major staging
    __shared__ float sBr[32];
    __shared__ float sOW[HID * NCLS];
    __shared__ float sOB[NCLS];

    const int tid = threadIdx.x;
    for (int i = tid; i < (INDIM + HID) * 32; i += BLK) sWraw[i] = W[i];
    for (int i = tid; i < 32; i += BLK)          sBr[i] = bias[i];
    for (int i = tid; i < HID * NCLS; i += BLK)  sOW[i] = ow[i];
    for (int i = tid; i < NCLS; i += BLK)        sOB[i] = ob[i];
    __syncthreads();

    const int gtid   = blockIdx.x * BLK + tid;
    const int sample = gtid >> 3;     // 8 lanes per sample
    const int m      = gtid & 7;      // hidden unit owned by this lane

    // One-time register gather. Pair layout: (i_col, j_col) and (f_col, o_col).
    u64 wXij[INDIM], wXfo[INDIM];
#pragma unroll
    for (int k = 0; k < INDIM; k++) {
        const float* r = sWraw + k * 32;
        wXij[k] = packab(r[m],      r[8 + m]);
        wXfo[k] = packab(r[16 + m], r[24 + m]);
    }
    // h-row weights in butterfly arrival order: position p delivers h[m^p].
    u64 wHij[HID], wHfo[HID];
#pragma unroll
    for (int p = 0; p < HID; p++) {
        const float* r = sWraw + (INDIM + (m ^ p)) * 32;
        wHij[p] = packab(r[m],      r[8 + m]);
        wHfo[p] = packab(r[16 + m], r[24 + m]);
    }
    const u64 bIJ = packab(sBr[m], sBr[8 + m]);
    const u64 bFO = packab(sBr[16 + m] + 1.0f, sBr[24 + m]);   // forget bias folded

    const float4* xp = (const float4*)(x + (size_t)sample * TSTEPS * INDIM);  // 7/step

    float c = 0.0f;
    float v[HID];                      // h in butterfly order: v[p] = h[m^p]
#pragma unroll
    for (int p = 0; p < HID; p++) v[p] = 0.0f;

#pragma unroll 1
    for (int t = 0; t < TSTEPS; t++) {
        // x for this step (8 lanes per sample issue identical addresses ->
        // coalescer dedups; unique DRAM traffic = 117 MB total).
        float4 X[7];
#pragma unroll
        for (int q = 0; q < 7; q++) X[q] = xp[t * 7 + q];

        u64 gij = bIJ, gfo = bFO;

#pragma unroll
        for (int ch = 0; ch < 7; ch++) {
#pragma unroll
            for (int j = 0; j < 4; j++) {
                float xs = (j == 0) ? X[ch].x : (j == 1) ? X[ch].y
                         : (j == 2) ? X[ch].z : X[ch].w;
                u64 xx = pack2(xs);
                gij = fma2(xx, wXij[4 * ch + j], gij);
                gfo = fma2(xx, wXfo[4 * ch + j], gfo);
            }
        }
#pragma unroll
        for (int p = 0; p < HID; p++) {
            u64 hh = pack2(v[p]);
            gij = fma2(hh, wHij[p], gij);
            gfo = fma2(hh, wHfo[p], gfo);
        }

        float gi, gj, gf, go;
        unpack2(gij, gi, gj);
        unpack2(gfo, gf, go);

        float ig = sigf(gi);
        float jt = tanh_exact(gj);
        float fg = sigf(gf);           // bias already folded in
        float og = sigf(go);
        c = c * fg + ig * jt;
        float h = tanh_exact(c) * og;

        // Butterfly all-gather of h within the 8-lane group.
        // v[p] = h of lane (m ^ p).
        v[0] = h;
        v[1] = __shfl_xor_sync(0xffffffffu, v[0], 1);
        v[2] = __shfl_xor_sync(0xffffffffu, v[0], 2);
        v[3] = __shfl_xor_sync(0xffffffffu, v[1], 2);
        v[4] = __shfl_xor_sync(0xffffffffu, v[0], 4);
        v[5] = __shfl_xor_sync(0xffffffffu, v[1], 4);
        v[6] = __shfl_xor_sync(0xffffffffu, v[2], 4);
        v[7] = __shfl_xor_sync(0xffffffffu, v[3], 4);
    }

    // Output projection: lane m==0 has v[p] = h[0^p] = h[p].
    if (m == 0) {
        float* op = out + (size_t)sample * NCLS;
#pragma unroll
        for (int n = 0; n < NCLS; n++) {
            float acc = sOB[n];
#pragma unroll
            for (int u = 0; u < HID; u++) acc += v[u] * sOW[u * NCLS + n];
            op[n] = acc;
        }
    }
}

extern "C" void kernel_launch(void* const* d_in, const int* in_sizes, int n_in,
                              void* d_out, int out_size) {
    const float* x  = (const float*)d_in[0];
    const float* W  = (const float*)d_in[1];
    const float* bl = (const float*)d_in[2];
    const float* ow = (const float*)d_in[3];
    const float* ob = (const float*)d_in[4];
    float* out = (float*)d_out;

    // 8 lanes per sample -> 262144 threads
    lstm_kernel<<<(BTOT * 8) / BLK, BLK>>>(x, W, bl, ow, ob, out);
}